// round 1
// baseline (speedup 1.0000x reference)
#include <cuda_runtime.h>
#include <cuda_bf16.h>

// MatrixFactorization: out[r] = dot(concat(Wd[dow[r]],Wt[time[r]],Wm[month[r]],Wdy[day[r]]),
//                                   W_item[dest[r]])
// N = 1048576, NUM_FACTOR = 128, NUM_DIM = 32.
//
// Strategy: one warp per row. Each lane loads one float4 of the 128-float item
// row (512B fully coalesced). The 4 small tables (total 9.4 KB) stay in L1 —
// lane l reads table (l/8) at float-offset (l%8)*4 of the gathered row.
// Per-lane dot, then 5-step shfl_xor butterfly reduce; lane 0 stores.
// Each warp processes ROWS_PER_WARP consecutive rows for index locality + ILP.

#define WARPS_PER_BLOCK 8
#define THREADS (WARPS_PER_BLOCK * 32)
#define ROWS_PER_WARP 16

__global__ __launch_bounds__(THREADS)
void mf_kernel(const int* __restrict__ dow,
               const int* __restrict__ tim,
               const int* __restrict__ mon,
               const int* __restrict__ day,
               const int* __restrict__ dest,
               const float* __restrict__ Wdow,
               const float* __restrict__ Wtim,
               const float* __restrict__ Wmon,
               const float* __restrict__ Wday,
               const float* __restrict__ Witem,
               float* __restrict__ out,
               int n)
{
    const int warp_id = blockIdx.x * WARPS_PER_BLOCK + (threadIdx.x >> 5);
    const int lane = threadIdx.x & 31;
    const int sub = lane >> 3;        // which small table (0..3)
    const int off = (lane & 7) * 4;   // float offset within 32-dim embedding

    // Per-lane pointers: each lane only ever reads "its" small table + its index array.
    const float* __restrict__ Wsub =
        (sub == 0) ? Wdow : (sub == 1) ? Wtim : (sub == 2) ? Wmon : Wday;
    const int* __restrict__ idx_arr =
        (sub == 0) ? dow : (sub == 1) ? tim : (sub == 2) ? mon : day;

    const int base = warp_id * ROWS_PER_WARP;

#pragma unroll
    for (int i = 0; i < ROWS_PER_WARP; i++) {
        const int r = base + i;
        if (r >= n) return;

        const int si = __ldg(idx_arr + r);   // small-table row (broadcast per 8 lanes)
        const int di = __ldg(dest + r);      // item row (broadcast across warp)

        const float4 u = *reinterpret_cast<const float4*>(Wsub + si * 32 + off);
        const float4 v = *reinterpret_cast<const float4*>(Witem + (long long)di * 128 + lane * 4);

        float s = u.x * v.x;
        s = fmaf(u.y, v.y, s);
        s = fmaf(u.z, v.z, s);
        s = fmaf(u.w, v.w, s);

        // Butterfly reduce across the warp.
        s += __shfl_xor_sync(0xFFFFFFFFu, s, 16);
        s += __shfl_xor_sync(0xFFFFFFFFu, s, 8);
        s += __shfl_xor_sync(0xFFFFFFFFu, s, 4);
        s += __shfl_xor_sync(0xFFFFFFFFu, s, 2);
        s += __shfl_xor_sync(0xFFFFFFFFu, s, 1);

        if (lane == 0) out[r] = s;
    }
}

extern "C" void kernel_launch(void* const* d_in, const int* in_sizes, int n_in,
                              void* d_out, int out_size)
{
    const int*   dow   = (const int*)d_in[0];
    const int*   tim   = (const int*)d_in[1];
    const int*   mon   = (const int*)d_in[2];
    const int*   day   = (const int*)d_in[3];
    const int*   dest  = (const int*)d_in[4];
    const float* Wdow  = (const float*)d_in[5];
    const float* Wtim  = (const float*)d_in[6];
    const float* Wmon  = (const float*)d_in[7];
    const float* Wday  = (const float*)d_in[8];
    const float* Witem = (const float*)d_in[9];
    float* out = (float*)d_out;

    const int n = in_sizes[0];
    const int rows_per_block = WARPS_PER_BLOCK * ROWS_PER_WARP;  // 128
    const int grid = (n + rows_per_block - 1) / rows_per_block;

    mf_kernel<<<grid, THREADS>>>(dow, tim, mon, day, dest,
                                 Wdow, Wtim, Wmon, Wday, Witem, out, n);
}

// round 2
// speedup vs baseline: 1.2343x; 1.2343x over previous
#include <cuda_runtime.h>
#include <cuda_bf16.h>

// MatrixFactorization: out[r] = dot(concat(Wd[dow],Wt[time],Wm[month],Wdy[day]), W_item[dest])
// N=1048576, NUM_FACTOR=128, NUM_DIM=32.
//
// R2 strategy: warp-per-row loads (keeps item gather fully coalesced and the
// tiny tables' loads broadcast within lane-octets), but reduction batched
// across BATCH=8 rows: 2 shuffles/row instead of 5, and the 8 row-sums land on
// lanes {0,16,8,24,4,20,12,28} with CONTIGUOUS output addresses -> one store
// wavefront per 8 rows instead of 8 predicated scalar stores.

#define WARPS_PER_BLOCK 8
#define THREADS (WARPS_PER_BLOCK * 32)
#define BATCH 8
#define ROWS_PER_WARP 16   // 2 batches of 8

__global__ __launch_bounds__(THREADS)
void mf_kernel(const int* __restrict__ dow,
               const int* __restrict__ tim,
               const int* __restrict__ mon,
               const int* __restrict__ day,
               const int* __restrict__ dest,
               const float* __restrict__ Wdow,
               const float* __restrict__ Wtim,
               const float* __restrict__ Wmon,
               const float* __restrict__ Wday,
               const float* __restrict__ Witem,
               float* __restrict__ out,
               int n)
{
    const int warp_id = blockIdx.x * WARPS_PER_BLOCK + (threadIdx.x >> 5);
    const int lane = threadIdx.x & 31;
    const int sub = lane >> 3;        // which small table (0..3)
    const int off = (lane & 7) * 4;   // float offset within 32-dim embedding

    const float* __restrict__ Wsub =
        (sub == 0) ? Wdow : (sub == 1) ? Wtim : (sub == 2) ? Wmon : Wday;
    const int* __restrict__ idx_arr =
        (sub == 0) ? dow : (sub == 1) ? tim : (sub == 2) ? mon : day;

    // After the merged reduction tree, the lane holding row i of the batch is:
    //   bit4(lane) = i bit0, bit3(lane) = i bit1, bit2(lane) = i bit2, bits 0-1 = 0
    const int rowid = ((lane >> 4) & 1) | (((lane >> 3) & 1) << 1) | (((lane >> 2) & 1) << 2);
    const bool is_writer = ((lane & 3) == 0);

    const int base = warp_id * ROWS_PER_WARP;

#pragma unroll
    for (int b = 0; b < ROWS_PER_WARP / BATCH; b++) {
        const int rb = base + b * BATCH;
        if (rb >= n) return;

        float s[BATCH];

        if (rb + BATCH <= n) {
#pragma unroll
            for (int i = 0; i < BATCH; i++) {
                const int r  = rb + i;
                const int si = __ldg(idx_arr + r);
                const int di = __ldg(dest + r);
                const float4 u = *reinterpret_cast<const float4*>(Wsub + si * 32 + off);
                const float4 v = *reinterpret_cast<const float4*>(Witem + (long long)di * 128 + lane * 4);
                float acc = u.x * v.x;
                acc = fmaf(u.y, v.y, acc);
                acc = fmaf(u.z, v.z, acc);
                acc = fmaf(u.w, v.w, acc);
                s[i] = acc;
            }
        } else {
#pragma unroll
            for (int i = 0; i < BATCH; i++) {
                const int r = rb + i;
                float acc = 0.0f;
                if (r < n) {
                    const int si = __ldg(idx_arr + r);
                    const int di = __ldg(dest + r);
                    const float4 u = *reinterpret_cast<const float4*>(Wsub + si * 32 + off);
                    const float4 v = *reinterpret_cast<const float4*>(Witem + (long long)di * 128 + lane * 4);
                    acc = u.x * v.x;
                    acc = fmaf(u.y, v.y, acc);
                    acc = fmaf(u.z, v.z, acc);
                    acc = fmaf(u.w, v.w, acc);
                }
                s[i] = acc;
            }
        }

        // Merged reduction: 16 shuffles for 8 rows (2/row) instead of 40 (5/row).
        // Stage 1: xor 16 on all 8 partials.
#pragma unroll
        for (int i = 0; i < BATCH; i++)
            s[i] += __shfl_xor_sync(0xFFFFFFFFu, s[i], 16);
        // Select by bit4: half-warp 0 keeps even rows, half-warp 1 keeps odd rows.
        float t[4];
#pragma unroll
        for (int i = 0; i < 4; i++)
            t[i] = (lane < 16) ? s[2 * i] : s[2 * i + 1];
        // Stage 2: xor 8.
#pragma unroll
        for (int i = 0; i < 4; i++)
            t[i] += __shfl_xor_sync(0xFFFFFFFFu, t[i], 8);
        // Select by bit3.
        float q[2];
#pragma unroll
        for (int i = 0; i < 2; i++)
            q[i] = ((lane & 8) == 0) ? t[2 * i] : t[2 * i + 1];
        // Stage 3: xor 4.
#pragma unroll
        for (int i = 0; i < 2; i++)
            q[i] += __shfl_xor_sync(0xFFFFFFFFu, q[i], 4);
        // Select by bit2.
        float z = ((lane & 4) == 0) ? q[0] : q[1];
        // Stages 4-5: xor 2, xor 1.
        z += __shfl_xor_sync(0xFFFFFFFFu, z, 2);
        z += __shfl_xor_sync(0xFFFFFFFFu, z, 1);

        // 8 writer lanes, contiguous addresses out[rb .. rb+7] -> ~1 wavefront.
        const int r_out = rb + rowid;
        if (is_writer && r_out < n) out[r_out] = z;
    }
}

extern "C" void kernel_launch(void* const* d_in, const int* in_sizes, int n_in,
                              void* d_out, int out_size)
{
    const int*   dow   = (const int*)d_in[0];
    const int*   tim   = (const int*)d_in[1];
    const int*   mon   = (const int*)d_in[2];
    const int*   day   = (const int*)d_in[3];
    const int*   dest  = (const int*)d_in[4];
    const float* Wdow  = (const float*)d_in[5];
    const float* Wtim  = (const float*)d_in[6];
    const float* Wmon  = (const float*)d_in[7];
    const float* Wday  = (const float*)d_in[8];
    const float* Witem = (const float*)d_in[9];
    float* out = (float*)d_out;

    const int n = in_sizes[0];
    const int rows_per_block = WARPS_PER_BLOCK * ROWS_PER_WARP;  // 128
    const int grid = (n + rows_per_block - 1) / rows_per_block;

    mf_kernel<<<grid, THREADS>>>(dow, tim, mon, day, dest,
                                 Wdow, Wtim, Wmon, Wday, Witem, out, n);
}

// round 3
// speedup vs baseline: 1.3716x; 1.1112x over previous
#include <cuda_runtime.h>
#include <cuda_bf16.h>

// MatrixFactorization: out[r] = dot(concat(Wd[dow],Wt[time],Wm[month],Wdy[day]), W_item[dest])
// N=1048576, NUM_FACTOR=128, NUM_DIM=32.
//
// R3: warp-per-row loads + batched reduction (R2) + VECTORIZED INDEX LOADS:
// per 8-row batch, indices come in as 2x int4 from the lane's own index array
// (octet-broadcast) and 2x int4 from dest (warp-broadcast) -> 4 LDG.128
// instead of 16 scalar LDGs per batch.

#define WARPS_PER_BLOCK 8
#define THREADS (WARPS_PER_BLOCK * 32)
#define BATCH 8
#define ROWS_PER_WARP 16   // 2 batches of 8

__global__ __launch_bounds__(THREADS)
void mf_kernel(const int* __restrict__ dow,
               const int* __restrict__ tim,
               const int* __restrict__ mon,
               const int* __restrict__ day,
               const int* __restrict__ dest,
               const float* __restrict__ Wdow,
               const float* __restrict__ Wtim,
               const float* __restrict__ Wmon,
               const float* __restrict__ Wday,
               const float* __restrict__ Witem,
               float* __restrict__ out,
               int n)
{
    const int warp_id = blockIdx.x * WARPS_PER_BLOCK + (threadIdx.x >> 5);
    const int lane = threadIdx.x & 31;
    const int sub = lane >> 3;        // which small table (0..3)
    const int off = (lane & 7) * 4;   // float offset within 32-dim embedding

    const float* __restrict__ Wsub =
        (sub == 0) ? Wdow : (sub == 1) ? Wtim : (sub == 2) ? Wmon : Wday;
    const int* __restrict__ idx_arr =
        (sub == 0) ? dow : (sub == 1) ? tim : (sub == 2) ? mon : day;

    // Lane that ends up holding row i of the batch after the merged tree:
    //   bit4(lane)=i bit0, bit3(lane)=i bit1, bit2(lane)=i bit2, bits0-1=0.
    const int rowid = ((lane >> 4) & 1) | (((lane >> 3) & 1) << 1) | (((lane >> 2) & 1) << 2);
    const bool is_writer = ((lane & 3) == 0);

    const int base = warp_id * ROWS_PER_WARP;
    if (base >= n) return;

#pragma unroll
    for (int b = 0; b < ROWS_PER_WARP / BATCH; b++) {
        const int rb = base + b * BATCH;

        // ---- Vectorized index loads: rb is 8-aligned -> 32B-aligned int4 ----
        int si_v[BATCH];
        int di_v[BATCH];
        {
            const int4 ia = *reinterpret_cast<const int4*>(idx_arr + rb);
            const int4 ib = *reinterpret_cast<const int4*>(idx_arr + rb + 4);
            const int4 da = *reinterpret_cast<const int4*>(dest + rb);
            const int4 db = *reinterpret_cast<const int4*>(dest + rb + 4);
            si_v[0] = ia.x; si_v[1] = ia.y; si_v[2] = ia.z; si_v[3] = ia.w;
            si_v[4] = ib.x; si_v[5] = ib.y; si_v[6] = ib.z; si_v[7] = ib.w;
            di_v[0] = da.x; di_v[1] = da.y; di_v[2] = da.z; di_v[3] = da.w;
            di_v[4] = db.x; di_v[5] = db.y; di_v[6] = db.z; di_v[7] = db.w;
        }

        float s[BATCH];
#pragma unroll
        for (int i = 0; i < BATCH; i++) {
            const float4 u = *reinterpret_cast<const float4*>(Wsub + si_v[i] * 32 + off);
            const float4 v = *reinterpret_cast<const float4*>(
                Witem + (long long)di_v[i] * 128 + lane * 4);
            float acc = u.x * v.x;
            acc = fmaf(u.y, v.y, acc);
            acc = fmaf(u.z, v.z, acc);
            acc = fmaf(u.w, v.w, acc);
            s[i] = acc;
        }

        // ---- Merged reduction: 16 shuffles for 8 rows ----
#pragma unroll
        for (int i = 0; i < BATCH; i++)
            s[i] += __shfl_xor_sync(0xFFFFFFFFu, s[i], 16);
        float t[4];
#pragma unroll
        for (int i = 0; i < 4; i++)
            t[i] = (lane < 16) ? s[2 * i] : s[2 * i + 1];
#pragma unroll
        for (int i = 0; i < 4; i++)
            t[i] += __shfl_xor_sync(0xFFFFFFFFu, t[i], 8);
        float q[2];
#pragma unroll
        for (int i = 0; i < 2; i++)
            q[i] = ((lane & 8) == 0) ? t[2 * i] : t[2 * i + 1];
#pragma unroll
        for (int i = 0; i < 2; i++)
            q[i] += __shfl_xor_sync(0xFFFFFFFFu, q[i], 4);
        float z = ((lane & 4) == 0) ? q[0] : q[1];
        z += __shfl_xor_sync(0xFFFFFFFFu, z, 2);
        z += __shfl_xor_sync(0xFFFFFFFFu, z, 1);

        // 8 writer lanes, contiguous out[rb..rb+7] -> one 32B sector.
        if (is_writer) out[rb + rowid] = z;
    }
}

extern "C" void kernel_launch(void* const* d_in, const int* in_sizes, int n_in,
                              void* d_out, int out_size)
{
    const int*   dow   = (const int*)d_in[0];
    const int*   tim   = (const int*)d_in[1];
    const int*   mon   = (const int*)d_in[2];
    const int*   day   = (const int*)d_in[3];
    const int*   dest  = (const int*)d_in[4];
    const float* Wdow  = (const float*)d_in[5];
    const float* Wtim  = (const float*)d_in[6];
    const float* Wmon  = (const float*)d_in[7];
    const float* Wday  = (const float*)d_in[8];
    const float* Witem = (const float*)d_in[9];
    float* out = (float*)d_out;

    const int n = in_sizes[0];
    const int rows_per_block = WARPS_PER_BLOCK * ROWS_PER_WARP;  // 128
    const int grid = (n + rows_per_block - 1) / rows_per_block;

    mf_kernel<<<grid, THREADS>>>(dow, tim, mon, day, dest,
                                 Wdow, Wtim, Wmon, Wday, Witem, out, n);
}